// round 1
// baseline (speedup 1.0000x reference)
#include <cuda_runtime.h>
#include <cstddef>

// ---------------- problem constants ----------------
#define C      64
#define CPAD   68          // padded row stride (floats) -> conflict-free LDS.128
#define NATOMS 200000
#define NP5    100000
#define LEN5   5
#define NP6    80000
#define LEN6   6

// ---------------- scratch (device globals; no allocation allowed) ----------
__device__ float g_sum5[(size_t)NATOMS * C];
__device__ float g_sum6[(size_t)NATOMS * C];
__device__ float g_cnt5[NATOMS];
__device__ float g_cnt6[NATOMS];

using u64 = unsigned long long;

// ---------------- packed fp32 helpers (sm_103a FFMA2 path) ----------------
__device__ __forceinline__ void lds2(u64 &a, u64 &b, const float *p) {
    unsigned s = (unsigned)__cvta_generic_to_shared(p);
    asm volatile("ld.shared.v2.b64 {%0,%1}, [%2];" : "=l"(a), "=l"(b) : "r"(s));
}
__device__ __forceinline__ void fma2(u64 &acc, u64 a, u64 b) {
    asm volatile("fma.rn.f32x2 %0, %1, %2, %0;" : "+l"(acc) : "l"(a), "l"(b));
}
__device__ __forceinline__ float hsum2(u64 a) {
    float lo, hi;
    asm volatile("mov.b64 {%0,%1}, %2;" : "=f"(lo), "=f"(hi) : "l"(a));
    return lo + hi;
}
__device__ __forceinline__ void red4(float *p, float4 v) {
    asm volatile("red.global.add.v4.f32 [%0], {%1,%2,%3,%4};"
                 :: "l"(p), "f"(v.x), "f"(v.y), "f"(v.z), "f"(v.w) : "memory");
}

// ---------------- zero accumulators ----------------
__global__ void zero_kernel() {
    size_t i = (size_t)blockIdx.x * blockDim.x + threadIdx.x;
    size_t stride = (size_t)gridDim.x * blockDim.x;
    float4 z = make_float4(0.f, 0.f, 0.f, 0.f);
    for (size_t k = i; k < (size_t)NATOMS * C / 4; k += stride) {
        ((float4 *)g_sum5)[k] = z;
        ((float4 *)g_sum6)[k] = z;
    }
    for (size_t k = i; k < NATOMS / 4; k += stride) {
        ((float4 *)g_cnt5)[k] = z;
        ((float4 *)g_cnt6)[k] = z;
    }
}

// ---------------- fused path kernel ----------------
// group of 64 threads (thread = out channel) handles one path; 8 groups / block.
// Stages: gather x[row] -> mix linear+relu residual -> 2x residual conv(k=3) ->
//         write xp_out + red.v4 scatter into atom sums.
template <int L>
__global__ __launch_bounds__(512, 1) void path_kernel(
    const float *__restrict__ x, const float *__restrict__ xp_in,
    const int *__restrict__ row,
    const float *__restrict__ Wa, const float *__restrict__ ba,
    const float *__restrict__ Wc, const float *__restrict__ bc,
    float *__restrict__ xp_out, int P)
{
    extern __shared__ float smem[];
    float *Wa_s = smem;                      // C*CPAD
    float *Wc_s = Wa_s + C * CPAD;           // 6*C*CPAD  ([d][k][cout][cinPad])
    float *ba_s = Wc_s + 6 * C * CPAD;       // C
    float *bc_s = ba_s + C;                  // 2*C
    float *vg   = bc_s + 2 * C;              // 8 * L * C
    int   *rows = (int *)(vg + 8 * L * C);   // 8 * L

    float *sum = (L == LEN5) ? g_sum5 : g_sum6;
    float *cnt = (L == LEN5) ? g_cnt5 : g_cnt6;

    int tid = threadIdx.x;
    // stage weights (Wa already [cout][cin]; Wc is [d][k][cin][cout] -> transpose)
    for (int i = tid; i < C * C; i += 512)
        Wa_s[(i / C) * CPAD + (i % C)] = Wa[i];
    for (int i = tid; i < 6 * C * C; i += 512) {
        int m = i / (C * C);
        int r = i - m * C * C;
        int ci = r / C, co = r - ci * C;
        Wc_s[(m * C + co) * CPAD + ci] = Wc[i];
    }
    if (tid < C)     ba_s[tid] = ba[tid];
    if (tid < 2 * C) bc_s[tid] = bc[tid];
    __syncthreads();

    int g = tid >> 6, t = tid & 63;
    float *vp = vg + g * (L * C);
    int   *rp = rows + g * L;
    int ngtot = gridDim.x * 8;
    int iters = (P + ngtot - 1) / ngtot;
    int p0 = blockIdx.x * 8 + g;

    for (int it = 0; it < iters; ++it) {
        int p = p0 + it * ngtot;
        bool act = p < P;

        if (act && t < L) rp[t] = row[p * L + t];
        __syncthreads();

        // gather x rows (float4-coalesced)
        if (act) {
            for (int item = t; item < L * 16; item += 64) {
                int l = item >> 4, q = item & 15;
                ((float4 *)vp)[l * 16 + q] =
                    ((const float4 *)x)[(size_t)rp[l] * 16 + q];
            }
        }
        __syncthreads();

        // mix: y[l][t] = ba[t] + sum_ci g[l][ci]*Wa[t][ci]
        float y[L];
        if (act) {
            u64 acc[L];
#pragma unroll
            for (int l = 0; l < L; l++) acc[l] = 0ull;
            const float *wrow = Wa_s + t * CPAD;
#pragma unroll 4
            for (int c = 0; c < 16; c++) {
                u64 w0, w1; lds2(w0, w1, wrow + 4 * c);
#pragma unroll
                for (int l = 0; l < L; l++) {
                    u64 a0, a1; lds2(a0, a1, vp + l * C + 4 * c);
                    fma2(acc[l], w0, a0);
                    fma2(acc[l], w1, a1);
                }
            }
#pragma unroll
            for (int l = 0; l < L; l++) y[l] = hsum2(acc[l]) + ba_s[t];
        }
        __syncthreads();  // all reads of gathered data done before overwrite

        if (act) {
            const float *xin = xp_in + (size_t)p * L * C;
#pragma unroll
            for (int l = 0; l < L; l++)
                vp[l * C + t] = xin[l * C + t] + fmaxf(y[l], 0.f);
        }
        __syncthreads();

        // 2 residual conv blocks (k=3, zero pad)
#pragma unroll
        for (int d = 0; d < 2; d++) {
            float h[L];
            if (act) {
                u64 acc[L];
#pragma unroll
                for (int l = 0; l < L; l++) acc[l] = 0ull;
                const float *w0r = Wc_s + ((d * 3 + 0) * C + t) * CPAD;
                const float *w1r = Wc_s + ((d * 3 + 1) * C + t) * CPAD;
                const float *w2r = Wc_s + ((d * 3 + 2) * C + t) * CPAD;
#pragma unroll 4
                for (int c = 0; c < 16; c++) {
                    u64 wa0, wa1, wb0, wb1, wc0, wc1;
                    lds2(wa0, wa1, w0r + 4 * c);
                    lds2(wb0, wb1, w1r + 4 * c);
                    lds2(wc0, wc1, w2r + 4 * c);
                    u64 a0[L], a1[L];
#pragma unroll
                    for (int l = 0; l < L; l++)
                        lds2(a0[l], a1[l], vp + l * C + 4 * c);
#pragma unroll
                    for (int l = 0; l < L; l++) {
                        if (l > 0)     { fma2(acc[l], wa0, a0[l - 1]); fma2(acc[l], wa1, a1[l - 1]); }
                                         fma2(acc[l], wb0, a0[l]);     fma2(acc[l], wb1, a1[l]);
                        if (l < L - 1) { fma2(acc[l], wc0, a0[l + 1]); fma2(acc[l], wc1, a1[l + 1]); }
                    }
                }
#pragma unroll
                for (int l = 0; l < L; l++)
                    h[l] = hsum2(acc[l]) + bc_s[d * C + t];
            }
            __syncthreads();
            if (act) {
#pragma unroll
                for (int l = 0; l < L; l++)
                    vp[l * C + t] += fmaxf(h[l], 0.f);
            }
            __syncthreads();
        }

        // write xp_out + scatter into atom accumulators
        if (act) {
            float *xo = xp_out + (size_t)p * L * C;
            for (int item = t; item < L * 16; item += 64) {
                int l = item >> 4, q = item & 15;
                float4 v = ((float4 *)vp)[l * 16 + q];
                ((float4 *)xo)[l * 16 + q] = v;
                red4(sum + (size_t)rp[l] * C + q * 4, v);
            }
            if (t < L) atomicAdd(&cnt[rp[t]], 1.0f);
        }
        __syncthreads();  // protect rp/vp for next iteration
    }
}

// ---------------- atom kernel: x_out = x + relu(m5 Wp5^T+bp5) + relu(m6 Wp6^T+bp6)
__global__ __launch_bounds__(256) void atoms_kernel(
    const float *__restrict__ x,
    const float *__restrict__ Wp5, const float *__restrict__ bp5,
    const float *__restrict__ Wp6, const float *__restrict__ bp6,
    float *__restrict__ xout)
{
    extern __shared__ float smem[];
    float *W5s = smem;
    float *W6s = W5s + C * CPAD;
    float *b5s = W6s + C * CPAD;
    float *b6s = b5s + C;
    float *ms  = b6s + C;  // [4 groups][8][C]

    int tid = threadIdx.x;
    for (int i = tid; i < C * C; i += 256) {
        W5s[(i / C) * CPAD + (i % C)] = Wp5[i];
        W6s[(i / C) * CPAD + (i % C)] = Wp6[i];
    }
    if (tid < C) { b5s[tid] = bp5[tid]; b6s[tid] = bp6[tid]; }
    __syncthreads();

    int g = tid >> 6, t = tid & 63;
    float *m5 = ms + g * 8 * C;
    float *m6 = m5 + 4 * C;
    int nq = NATOMS / 4;
    int qstride = gridDim.x * 4;
    int iters = (nq + qstride - 1) / qstride;
    int q0 = blockIdx.x * 4 + g;

    for (int it = 0; it < iters; ++it) {
        int q = q0 + it * qstride;
        bool act = q < nq;
        if (act) {
#pragma unroll
            for (int r = 0; r < 4; r++) {
                int a = q * 4 + r;
                float c5 = fmaxf(g_cnt5[a], 1.f);
                float c6 = fmaxf(g_cnt6[a], 1.f);
                m5[r * C + t] = g_sum5[(size_t)a * C + t] / c5;
                m6[r * C + t] = g_sum6[(size_t)a * C + t] / c6;
            }
        }
        __syncthreads();
        if (act) {
            u64 a5[4], a6[4];
#pragma unroll
            for (int r = 0; r < 4; r++) { a5[r] = 0ull; a6[r] = 0ull; }
            const float *w5r = W5s + t * CPAD;
            const float *w6r = W6s + t * CPAD;
#pragma unroll 4
            for (int c = 0; c < 16; c++) {
                u64 w50, w51, w60, w61;
                lds2(w50, w51, w5r + 4 * c);
                lds2(w60, w61, w6r + 4 * c);
#pragma unroll
                for (int r = 0; r < 4; r++) {
                    u64 x0, x1;
                    lds2(x0, x1, m5 + r * C + 4 * c);
                    fma2(a5[r], w50, x0); fma2(a5[r], w51, x1);
                    u64 y0, y1;
                    lds2(y0, y1, m6 + r * C + 4 * c);
                    fma2(a6[r], w60, y0); fma2(a6[r], w61, y1);
                }
            }
#pragma unroll
            for (int r = 0; r < 4; r++) {
                int a = q * 4 + r;
                float v = x[(size_t)a * C + t]
                        + fmaxf(hsum2(a5[r]) + b5s[t], 0.f)
                        + fmaxf(hsum2(a6[r]) + b6s[t], 0.f);
                xout[(size_t)a * C + t] = v;
            }
        }
        __syncthreads();
    }
}

// ---------------- launch ----------------
extern "C" void kernel_launch(void *const *d_in, const int *in_sizes, int n_in,
                              void *d_out, int out_size)
{
    const float *x    = (const float *)d_in[0];
    const float *xp5  = (const float *)d_in[1];
    const float *xp6  = (const float *)d_in[2];
    const int   *row5 = (const int *)d_in[3];
    // d_in[4] = col5 (identity arange), unused
    const int   *row6 = (const int *)d_in[5];
    // d_in[6] = col6 (identity arange), unused
    const float *Wa5 = (const float *)d_in[7];
    const float *ba5 = (const float *)d_in[8];
    const float *Wa6 = (const float *)d_in[9];
    const float *ba6 = (const float *)d_in[10];
    const float *Wp5 = (const float *)d_in[11];
    const float *bp5 = (const float *)d_in[12];
    const float *Wp6 = (const float *)d_in[13];
    const float *bp6 = (const float *)d_in[14];
    const float *Wc5 = (const float *)d_in[15];
    const float *bc5 = (const float *)d_in[16];
    const float *Wc6 = (const float *)d_in[17];
    const float *bc6 = (const float *)d_in[18];

    float *x_out   = (float *)d_out;
    float *xp5_out = x_out + (size_t)NATOMS * C;
    float *xp6_out = xp5_out + (size_t)NP5 * LEN5 * C;

    constexpr int smem_base = (C * CPAD + 6 * C * CPAD + C + 2 * C) * 4;
    constexpr int smem5 = smem_base + 8 * LEN5 * C * 4 + 8 * LEN5 * 4;
    constexpr int smem6 = smem_base + 8 * LEN6 * C * 4 + 8 * LEN6 * 4;
    constexpr int smemA = (2 * C * CPAD + 2 * C + 4 * 8 * C) * 4;

    static_assert(smem5 < 227 * 1024 && smem6 < 227 * 1024, "smem");

    cudaFuncSetAttribute((const void *)path_kernel<LEN5>,
                         cudaFuncAttributeMaxDynamicSharedMemorySize, smem5);
    cudaFuncSetAttribute((const void *)path_kernel<LEN6>,
                         cudaFuncAttributeMaxDynamicSharedMemorySize, smem6);
    cudaFuncSetAttribute((const void *)atoms_kernel,
                         cudaFuncAttributeMaxDynamicSharedMemorySize, smemA);

    zero_kernel<<<1024, 256>>>();

    path_kernel<LEN5><<<304, 512, smem5>>>(x, xp5, row5, Wa5, ba5, Wc5, bc5,
                                           xp5_out, NP5);
    path_kernel<LEN6><<<304, 512, smem6>>>(x, xp6, row6, Wa6, ba6, Wc6, bc6,
                                           xp6_out, NP6);

    atoms_kernel<<<304, 256, smemA>>>(x, Wp5, bp5, Wp6, bp6, x_out);
}

// round 2
// speedup vs baseline: 1.3922x; 1.3922x over previous
#include <cuda_runtime.h>
#include <cstddef>

// ---------------- problem constants ----------------
#define C      64
#define CPAD   68          // padded row stride (floats) -> conflict-free LDS.128
#define NATOMS 200000
#define NP5    100000
#define LEN5   5
#define NP6    80000
#define LEN6   6

// ---------------- scratch (device globals; no allocation allowed) ----------
__device__ float g_sum5[(size_t)NATOMS * C];
__device__ float g_sum6[(size_t)NATOMS * C];
__device__ float g_cnt5[NATOMS];
__device__ float g_cnt6[NATOMS];

using u64 = unsigned long long;

// ---------------- packed fp32 helpers (sm_103a FFMA2 path) ----------------
__device__ __forceinline__ void lds2(u64 &a, u64 &b, const float *p) {
    unsigned s = (unsigned)__cvta_generic_to_shared(p);
    asm volatile("ld.shared.v2.b64 {%0,%1}, [%2];" : "=l"(a), "=l"(b) : "r"(s));
}
__device__ __forceinline__ void fma2(u64 &acc, u64 a, u64 b) {
    asm volatile("fma.rn.f32x2 %0, %1, %2, %0;" : "+l"(acc) : "l"(a), "l"(b));
}
__device__ __forceinline__ float hsum2(u64 a) {
    float lo, hi;
    asm volatile("mov.b64 {%0,%1}, %2;" : "=f"(lo), "=f"(hi) : "l"(a));
    return lo + hi;
}
__device__ __forceinline__ void red4(float *p, float4 v) {
    asm volatile("red.global.add.v4.f32 [%0], {%1,%2,%3,%4};"
                 :: "l"(p), "f"(v.x), "f"(v.y), "f"(v.z), "f"(v.w) : "memory");
}
// named barrier for a 64-thread group (ids 1..8; __syncthreads owns id 0)
__device__ __forceinline__ void barg(int id) {
    asm volatile("bar.sync %0, 64;" :: "r"(id) : "memory");
}

// ---------------- zero accumulators ----------------
__global__ void zero_kernel() {
    size_t i = (size_t)blockIdx.x * blockDim.x + threadIdx.x;
    size_t stride = (size_t)gridDim.x * blockDim.x;
    float4 z = make_float4(0.f, 0.f, 0.f, 0.f);
    for (size_t k = i; k < (size_t)NATOMS * C / 4; k += stride) {
        ((float4 *)g_sum5)[k] = z;
        ((float4 *)g_sum6)[k] = z;
    }
    for (size_t k = i; k < NATOMS / 4; k += stride) {
        ((float4 *)g_cnt5)[k] = z;
        ((float4 *)g_cnt6)[k] = z;
    }
}

// ---------------- fused path kernel ----------------
// 64-thread group (thread = out channel) handles NP paths per iteration;
// weight smem reads amortized over NP*L accumulator rows.
template <int L, int NP>
__global__ __launch_bounds__(512, 1) void path_kernel(
    const float *__restrict__ x, const float *__restrict__ xp_in,
    const int *__restrict__ row,
    const float *__restrict__ Wa, const float *__restrict__ ba,
    const float *__restrict__ Wc, const float *__restrict__ bc,
    float *__restrict__ xp_out, int P)
{
    extern __shared__ float smem[];
    float *Wa_s = smem;                      // C*CPAD
    float *Wc_s = Wa_s + C * CPAD;           // 6*C*CPAD  ([d][k][cout][cinPad])
    float *ba_s = Wc_s + 6 * C * CPAD;       // C
    float *bc_s = ba_s + C;                  // 2*C
    float *vg   = bc_s + 2 * C;              // 8 * NP * L * C
    int   *rows = (int *)(vg + 8 * NP * L * C);   // 8 * NP * L

    float *sum = (L == LEN5) ? g_sum5 : g_sum6;
    float *cnt = (L == LEN5) ? g_cnt5 : g_cnt6;

    int tid = threadIdx.x;
    // stage weights (Wa already [cout][cin]; Wc is [d][k][cin][cout] -> transpose)
    for (int i = tid; i < C * C; i += 512)
        Wa_s[(i / C) * CPAD + (i % C)] = Wa[i];
    for (int i = tid; i < 6 * C * C; i += 512) {
        int m = i / (C * C);
        int r = i - m * C * C;
        int ci = r / C, co = r - ci * C;
        Wc_s[(m * C + co) * CPAD + ci] = Wc[i];
    }
    if (tid < C)     ba_s[tid] = ba[tid];
    if (tid < 2 * C) bc_s[tid] = bc[tid];
    __syncthreads();

    int g = tid >> 6, t = tid & 63;
    int bid = g + 1;                         // named barrier id
    float *vp = vg + g * (NP * L * C);
    int   *rp = rows + g * (NP * L);
    int NG = gridDim.x * 8;
    int iters = (P + NG * NP - 1) / (NG * NP);
    int G = blockIdx.x * 8 + g;

    for (int it = 0; it < iters; ++it) {
        int pbase = (it * NG + G) * NP;

        // load row indices for the NP paths
        if (t < NP * L) {
            int j = t / L, l = t - j * L;
            int p = pbase + j;
            rp[t] = (p < P) ? row[p * L + l] : 0;
        }
        barg(bid);

        // gather x rows (float4-coalesced)
        for (int item = t; item < NP * L * 16; item += 64) {
            int r = item >> 4, q = item & 15;       // r = j*L + l
            if (pbase + r / L < P)
                ((float4 *)vp)[r * 16 + q] =
                    ((const float4 *)x)[(size_t)rp[r] * 16 + q];
        }
        barg(bid);

        // ---- mix: y[j][l][t] = ba[t] + sum_ci g[j][l][ci]*Wa[t][ci]
        float y[NP][L];
        {
            u64 acc[NP][L];
#pragma unroll
            for (int j = 0; j < NP; j++)
#pragma unroll
                for (int l = 0; l < L; l++) acc[j][l] = 0ull;
            const float *wrow = Wa_s + t * CPAD;
#pragma unroll 4
            for (int c = 0; c < 16; c++) {
                u64 w0, w1; lds2(w0, w1, wrow + 4 * c);
#pragma unroll
                for (int j = 0; j < NP; j++)
#pragma unroll
                    for (int l = 0; l < L; l++) {
                        u64 a0, a1; lds2(a0, a1, vp + (j * L + l) * C + 4 * c);
                        fma2(acc[j][l], w0, a0);
                        fma2(acc[j][l], w1, a1);
                    }
            }
#pragma unroll
            for (int j = 0; j < NP; j++)
#pragma unroll
                for (int l = 0; l < L; l++) y[j][l] = hsum2(acc[j][l]) + ba_s[t];
        }
        barg(bid);  // all reads of gathered data done before overwrite

#pragma unroll
        for (int j = 0; j < NP; j++) {
            if (pbase + j < P) {
                const float *xin = xp_in + (size_t)(pbase + j) * L * C;
#pragma unroll
                for (int l = 0; l < L; l++)
                    vp[(j * L + l) * C + t] = xin[l * C + t] + fmaxf(y[j][l], 0.f);
            }
        }
        barg(bid);

        // ---- 2 residual conv blocks (k=3, zero pad)
#pragma unroll
        for (int d = 0; d < 2; d++) {
            float h[NP][L];
            {
                u64 acc[NP][L];
#pragma unroll
                for (int j = 0; j < NP; j++)
#pragma unroll
                    for (int l = 0; l < L; l++) acc[j][l] = 0ull;
                const float *w0r = Wc_s + ((d * 3 + 0) * C + t) * CPAD;
                const float *w1r = Wc_s + ((d * 3 + 1) * C + t) * CPAD;
                const float *w2r = Wc_s + ((d * 3 + 2) * C + t) * CPAD;
#pragma unroll 2
                for (int c = 0; c < 16; c++) {
                    u64 wa0, wa1, wb0, wb1, wc0, wc1;
                    lds2(wa0, wa1, w0r + 4 * c);
                    lds2(wb0, wb1, w1r + 4 * c);
                    lds2(wc0, wc1, w2r + 4 * c);
#pragma unroll
                    for (int j = 0; j < NP; j++) {
                        u64 a0[L], a1[L];
#pragma unroll
                        for (int l = 0; l < L; l++)
                            lds2(a0[l], a1[l], vp + (j * L + l) * C + 4 * c);
#pragma unroll
                        for (int l = 0; l < L; l++) {
                            if (l > 0)     { fma2(acc[j][l], wa0, a0[l - 1]); fma2(acc[j][l], wa1, a1[l - 1]); }
                                             fma2(acc[j][l], wb0, a0[l]);     fma2(acc[j][l], wb1, a1[l]);
                            if (l < L - 1) { fma2(acc[j][l], wc0, a0[l + 1]); fma2(acc[j][l], wc1, a1[l + 1]); }
                        }
                    }
                }
#pragma unroll
                for (int j = 0; j < NP; j++)
#pragma unroll
                    for (int l = 0; l < L; l++)
                        h[j][l] = hsum2(acc[j][l]) + bc_s[d * C + t];
            }
            barg(bid);
#pragma unroll
            for (int j = 0; j < NP; j++)
#pragma unroll
                for (int l = 0; l < L; l++)
                    vp[(j * L + l) * C + t] += fmaxf(h[j][l], 0.f);
            barg(bid);
        }

        // ---- write xp_out + scatter into atom accumulators
        for (int item = t; item < NP * L * 16; item += 64) {
            int r = item >> 4, q = item & 15;       // r = j*L + l
            int j = r / L;
            if (pbase + j < P) {
                float4 v = ((float4 *)vp)[r * 16 + q];
                ((float4 *)(xp_out + (size_t)(pbase + j) * L * C))[(r - j * L) * 16 + q] = v;
                red4(sum + (size_t)rp[r] * C + q * 4, v);
            }
        }
        if (t < NP * L && pbase + t / L < P)
            atomicAdd(&cnt[rp[t]], 1.0f);
        barg(bid);  // protect rp/vp for next iteration
    }
}

// ---------------- atom kernel: x_out = x + relu(m5 Wp5^T+bp5) + relu(m6 Wp6^T+bp6)
__global__ __launch_bounds__(256) void atoms_kernel(
    const float *__restrict__ x,
    const float *__restrict__ Wp5, const float *__restrict__ bp5,
    const float *__restrict__ Wp6, const float *__restrict__ bp6,
    float *__restrict__ xout)
{
    extern __shared__ float smem[];
    float *W5s = smem;
    float *W6s = W5s + C * CPAD;
    float *b5s = W6s + C * CPAD;
    float *b6s = b5s + C;
    float *ms  = b6s + C;  // [4 groups][8][C]

    int tid = threadIdx.x;
    for (int i = tid; i < C * C; i += 256) {
        W5s[(i / C) * CPAD + (i % C)] = Wp5[i];
        W6s[(i / C) * CPAD + (i % C)] = Wp6[i];
    }
    if (tid < C) { b5s[tid] = bp5[tid]; b6s[tid] = bp6[tid]; }
    __syncthreads();

    int g = tid >> 6, t = tid & 63;
    int bid = g + 1;
    float *m5 = ms + g * 8 * C;
    float *m6 = m5 + 4 * C;
    int nq = NATOMS / 4;
    int qstride = gridDim.x * 4;
    int iters = (nq + qstride - 1) / qstride;
    int q0 = blockIdx.x * 4 + g;

    for (int it = 0; it < iters; ++it) {
        int q = q0 + it * qstride;
        bool act = q < nq;
        if (act) {
#pragma unroll
            for (int r = 0; r < 4; r++) {
                int a = q * 4 + r;
                float c5 = fmaxf(g_cnt5[a], 1.f);
                float c6 = fmaxf(g_cnt6[a], 1.f);
                m5[r * C + t] = g_sum5[(size_t)a * C + t] / c5;
                m6[r * C + t] = g_sum6[(size_t)a * C + t] / c6;
            }
        }
        barg(bid);
        if (act) {
            u64 a5[4], a6[4];
#pragma unroll
            for (int r = 0; r < 4; r++) { a5[r] = 0ull; a6[r] = 0ull; }
            const float *w5r = W5s + t * CPAD;
            const float *w6r = W6s + t * CPAD;
#pragma unroll 4
            for (int c = 0; c < 16; c++) {
                u64 w50, w51, w60, w61;
                lds2(w50, w51, w5r + 4 * c);
                lds2(w60, w61, w6r + 4 * c);
#pragma unroll
                for (int r = 0; r < 4; r++) {
                    u64 x0, x1;
                    lds2(x0, x1, m5 + r * C + 4 * c);
                    fma2(a5[r], w50, x0); fma2(a5[r], w51, x1);
                    u64 y0, y1;
                    lds2(y0, y1, m6 + r * C + 4 * c);
                    fma2(a6[r], w60, y0); fma2(a6[r], w61, y1);
                }
            }
#pragma unroll
            for (int r = 0; r < 4; r++) {
                int a = q * 4 + r;
                float v = x[(size_t)a * C + t]
                        + fmaxf(hsum2(a5[r]) + b5s[t], 0.f)
                        + fmaxf(hsum2(a6[r]) + b6s[t], 0.f);
                xout[(size_t)a * C + t] = v;
            }
        }
        barg(bid);
    }
}

// ---------------- launch ----------------
extern "C" void kernel_launch(void *const *d_in, const int *in_sizes, int n_in,
                              void *d_out, int out_size)
{
    const float *x    = (const float *)d_in[0];
    const float *xp5  = (const float *)d_in[1];
    const float *xp6  = (const float *)d_in[2];
    const int   *row5 = (const int *)d_in[3];
    // d_in[4] = col5 (identity arange), unused
    const int   *row6 = (const int *)d_in[5];
    // d_in[6] = col6 (identity arange), unused
    const float *Wa5 = (const float *)d_in[7];
    const float *ba5 = (const float *)d_in[8];
    const float *Wa6 = (const float *)d_in[9];
    const float *ba6 = (const float *)d_in[10];
    const float *Wp5 = (const float *)d_in[11];
    const float *bp5 = (const float *)d_in[12];
    const float *Wp6 = (const float *)d_in[13];
    const float *bp6 = (const float *)d_in[14];
    const float *Wc5 = (const float *)d_in[15];
    const float *bc5 = (const float *)d_in[16];
    const float *Wc6 = (const float *)d_in[17];
    const float *bc6 = (const float *)d_in[18];

    float *x_out   = (float *)d_out;
    float *xp5_out = x_out + (size_t)NATOMS * C;
    float *xp6_out = xp5_out + (size_t)NP5 * LEN5 * C;

    constexpr int NPP5 = 4;   // paths per group, L=5
    constexpr int NPP6 = 3;   // paths per group, L=6

    constexpr int smem_base = (C * CPAD + 6 * C * CPAD + C + 2 * C) * 4;
    constexpr int smem5 = smem_base + 8 * NPP5 * LEN5 * C * 4 + 8 * NPP5 * LEN5 * 4;
    constexpr int smem6 = smem_base + 8 * NPP6 * LEN6 * C * 4 + 8 * NPP6 * LEN6 * 4;
    constexpr int smemA = (2 * C * CPAD + 2 * C + 4 * 8 * C) * 4;

    static_assert(smem5 < 227 * 1024 && smem6 < 227 * 1024, "smem");

    cudaFuncSetAttribute((const void *)path_kernel<LEN5, NPP5>,
                         cudaFuncAttributeMaxDynamicSharedMemorySize, smem5);
    cudaFuncSetAttribute((const void *)path_kernel<LEN6, NPP6>,
                         cudaFuncAttributeMaxDynamicSharedMemorySize, smem6);
    cudaFuncSetAttribute((const void *)atoms_kernel,
                         cudaFuncAttributeMaxDynamicSharedMemorySize, smemA);

    zero_kernel<<<1024, 256>>>();

    path_kernel<LEN5, NPP5><<<304, 512, smem5>>>(x, xp5, row5, Wa5, ba5, Wc5, bc5,
                                                 xp5_out, NP5);
    path_kernel<LEN6, NPP6><<<304, 512, smem6>>>(x, xp6, row6, Wa6, ba6, Wc6, bc6,
                                                 xp6_out, NP6);

    atoms_kernel<<<760, 256, smemA>>>(x, Wp5, bp5, Wp6, bp6, x_out);
}